// round 1
// baseline (speedup 1.0000x reference)
#include <cuda_runtime.h>
#include <math.h>

#define WIDTHW 16
#define HIDD 512
#define NHEADS 8
#define DKH 64
#define SEQ 1024
#define BBATCH 4
#define PADL 1056   // SEQ + 2*WIDTH

// ---------------- scratch (device globals; no allocation allowed) -----------
__device__ float g_xp   [2][(size_t)BBATCH*PADL*HIDD];
__device__ float g_qkv  [2][(size_t)BBATCH*PADL*3*HIDD];
__device__ float g_attn [2][(size_t)BBATCH*PADL*HIDD];
__device__ float g_fa   [2][(size_t)BBATCH*PADL*HIDD];
__device__ float g_state[2][(size_t)BBATCH*SEQ*HIDD];
__device__ float g_proj [2][(size_t)BBATCH*SEQ*2*HIDD];

// ---------------- padded input build ----------------------------------------
// xp[b,t,c]: t<16 -> fw_pad[t,c]; 16<=t<1040 -> src[b,t-16,c]; else bw_pad[t-1040,c]
__global__ void build_pad_kernel(const float* __restrict__ src,
                                 const float* __restrict__ fp,
                                 const float* __restrict__ bp,
                                 float* __restrict__ xp)
{
    int idx = blockIdx.x * blockDim.x + threadIdx.x;
    const int total = BBATCH * PADL * HIDD;
    if (idx >= total) return;
    int c = idx % HIDD;
    int t = (idx / HIDD) % PADL;
    int b = idx / (HIDD * PADL);
    float v;
    if (t < WIDTHW)               v = fp[t * HIDD + c];
    else if (t < WIDTHW + SEQ)    v = src[((size_t)b * SEQ + (t - WIDTHW)) * HIDD + c];
    else                          v = bp[(t - WIDTHW - SEQ) * HIDD + c];
    xp[idx] = v;
}

// ---------------- generic NT GEMM: C[M,N] = A[M,K] * W[N,K]^T + bias[N] -----
// A row-major MxK, W row-major NxK (torch Linear layout). M%128==0, N%128==0, K%16==0.
__global__ void __launch_bounds__(256, 1)
gemm_nt_bias(const float* __restrict__ A, const float* __restrict__ W,
             const float* __restrict__ bias, float* __restrict__ C,
             int M, int N, int K)
{
    constexpr int BM = 128, BN = 128, BK = 16;
    __shared__ float As[BK][BM + 4];
    __shared__ float Bs[BK][BN + 4];

    const int tid = threadIdx.x;
    const int bx = blockIdx.x;   // N tile
    const int by = blockIdx.y;   // M tile

    const float* Ab = A + (size_t)by * BM * K;
    const float* Wb = W + (size_t)bx * BN * K;

    float acc[8][8];
#pragma unroll
    for (int i = 0; i < 8; i++)
#pragma unroll
        for (int j = 0; j < 8; j++) acc[i][j] = 0.f;

    const int tr = (tid >> 4) << 3;   // 0..120
    const int tc = (tid & 15) << 3;   // 0..120

    for (int k0 = 0; k0 < K; k0 += BK) {
#pragma unroll
        for (int p = 0; p < 2; p++) {
            int idx = tid + p * 256;
            int row = idx >> 2;            // 0..127
            int kq  = (idx & 3) << 2;      // 0,4,8,12
            float4 va = *(const float4*)(Ab + (size_t)row * K + k0 + kq);
            As[kq + 0][row] = va.x; As[kq + 1][row] = va.y;
            As[kq + 2][row] = va.z; As[kq + 3][row] = va.w;
            float4 vb = *(const float4*)(Wb + (size_t)row * K + k0 + kq);
            Bs[kq + 0][row] = vb.x; Bs[kq + 1][row] = vb.y;
            Bs[kq + 2][row] = vb.z; Bs[kq + 3][row] = vb.w;
        }
        __syncthreads();
#pragma unroll
        for (int kk = 0; kk < BK; kk++) {
            float a[8], bv[8];
#pragma unroll
            for (int i = 0; i < 8; i++) a[i] = As[kk][tr + i];
#pragma unroll
            for (int j = 0; j < 8; j++) bv[j] = Bs[kk][tc + j];
#pragma unroll
            for (int i = 0; i < 8; i++)
#pragma unroll
                for (int j = 0; j < 8; j++) acc[i][j] += a[i] * bv[j];
        }
        __syncthreads();
    }

#pragma unroll
    for (int i = 0; i < 8; i++) {
        size_t row = (size_t)(by * BM + tr + i);
#pragma unroll
        for (int j = 0; j < 8; j++) {
            int col = bx * BN + tc + j;
            C[row * N + col] = acc[i][j] + bias[col];
        }
    }
}

// ---------------- banded attention ------------------------------------------
// qkv: [B, PAD, 1536] (q | k | v). out: [B, PAD, 512].
// dir==0 (fw): keys j in [max(0,i-17), i];  dir==1 (bw): j in [i, min(PAD-1,i+17)]
__global__ void band_attn_kernel(const float* __restrict__ qkv,
                                 float* __restrict__ out, int dir)
{
    const int warp = threadIdx.x >> 5;
    const int lane = threadIdx.x & 31;
    const int i = blockIdx.x * 8 + warp;                 // query index
    if (i >= PADL) return;
    const int bh = blockIdx.y;
    const int b = bh >> 3, h = bh & 7;

    const float* base = qkv + (size_t)b * PADL * (3 * HIDD);
    const int hc = h * DKH + 2 * lane;

    const float q0 = base[(size_t)i * (3 * HIDD) + hc];
    const float q1 = base[(size_t)i * (3 * HIDD) + hc + 1];

    int j0, j1;
    if (dir == 0) { j0 = max(0, i - (WIDTHW + 1)); j1 = i; }
    else          { j0 = i; j1 = min(PADL - 1, i + (WIDTHW + 1)); }

    float s[WIDTHW + 2];
    float mx = -1e30f;
#pragma unroll
    for (int t = 0; t < WIDTHW + 2; t++) {
        int j = j0 + t;
        bool valid = (j <= j1);
        int jc = valid ? j : j1;
        const float* kp = base + (size_t)jc * (3 * HIDD) + HIDD + hc;
        float p = q0 * kp[0] + q1 * kp[1];
#pragma unroll
        for (int o = 16; o > 0; o >>= 1) p += __shfl_xor_sync(0xffffffffu, p, o);
        p *= 0.125f;                       // 1/sqrt(64)
        s[t] = valid ? p : -1e30f;
        mx = fmaxf(mx, s[t]);
    }
    float den = 0.f;
#pragma unroll
    for (int t = 0; t < WIDTHW + 2; t++) { s[t] = __expf(s[t] - mx); den += s[t]; }
    const float inv = 1.f / den;

    float o0 = 0.f, o1 = 0.f;
#pragma unroll
    for (int t = 0; t < WIDTHW + 2; t++) {
        int j = j0 + t; if (j > j1) j = j1;
        const float* vp = base + (size_t)j * (3 * HIDD) + 2 * HIDD + hc;
        o0 += s[t] * vp[0];
        o1 += s[t] * vp[1];
    }
    float* op = out + ((size_t)b * PADL + i) * HIDD + hc;
    op[0] = o0 * inv;
    op[1] = o1 * inv;
}

// ---------------- rel-position combine --------------------------------------
// fo[b,t,c] = fa[b,16+t,c] + sum_{k=0..16} w[k] * fa[b,off+t+k,c]
__global__ void rel_combine_kernel(const float* __restrict__ fa,
                                   const float* __restrict__ w,
                                   float* __restrict__ fo, int off)
{
    int idx = blockIdx.x * blockDim.x + threadIdx.x;
    const int total = BBATCH * SEQ * HIDD;
    if (idx >= total) return;
    int c = idx & (HIDD - 1);
    int t = (idx >> 9) & (SEQ - 1);
    int b = idx >> 19;
    const float* base = fa + (size_t)b * PADL * HIDD + c;
    float acc = base[(size_t)(WIDTHW + t) * HIDD];
#pragma unroll
    for (int k = 0; k <= WIDTHW; k++)
        acc += __ldg(&w[k]) * base[(size_t)(off + t + k) * HIDD];
    fo[idx] = acc;
}

// ---------------- highway elementwise ---------------------------------------
// proj: [4096, 1024]; x: [4096, 512] (updated in place). Optionally mirror
// the result to outp (row stride 1024, column offset coloff).
__global__ void highway_elem_kernel(const float* __restrict__ proj,
                                    float* __restrict__ x,
                                    float* __restrict__ outp, int coloff)
{
    int idx = blockIdx.x * blockDim.x + threadIdx.x;
    const int total = BBATCH * SEQ * HIDD;
    if (idx >= total) return;
    int r = idx >> 9;
    int c = idx & (HIDD - 1);
    float nl = proj[(size_t)r * (2 * HIDD) + c];
    float gz = proj[(size_t)r * (2 * HIDD) + HIDD + c];
    float g = 1.f / (1.f + __expf(-gz));
    float res = g * x[idx] + (1.f - g) * fmaxf(nl, 0.f);
    x[idx] = res;
    if (outp) outp[(size_t)r * (2 * HIDD) + coloff + c] = res;
}

// ---------------- launcher ----------------------------------------------------
extern "C" void kernel_launch(void* const* d_in, const int* in_sizes, int n_in,
                              void* d_out, int out_size)
{
    const float* inputs   = (const float*)d_in[0];
    // d_in[1] = masks (unused)
    const float* fw_lin_w = (const float*)d_in[2];
    const float* fw_lin_b = (const float*)d_in[3];
    const float* bw_lin_w = (const float*)d_in[4];
    const float* bw_lin_b = (const float*)d_in[5];
    const float* fw_hw_w  = (const float*)d_in[6];
    const float* fw_hw_b  = (const float*)d_in[7];
    const float* bw_hw_w  = (const float*)d_in[8];
    const float* bw_hw_b  = (const float*)d_in[9];
    const float* fw_pad   = (const float*)d_in[10];
    const float* bw_pad   = (const float*)d_in[11];
    const float* fw_rel   = (const float*)d_in[12];
    const float* bw_rel   = (const float*)d_in[13];
    float* out = (float*)d_out;

    float *xpB, *qkvB, *attnB, *faB, *stateB, *projB;
    cudaGetSymbolAddress((void**)&xpB,    g_xp);
    cudaGetSymbolAddress((void**)&qkvB,   g_qkv);
    cudaGetSymbolAddress((void**)&attnB,  g_attn);
    cudaGetSymbolAddress((void**)&faB,    g_fa);
    cudaGetSymbolAddress((void**)&stateB, g_state);
    cudaGetSymbolAddress((void**)&projB,  g_proj);

    const size_t szXP    = (size_t)BBATCH * PADL * HIDD;
    const size_t szQKV   = (size_t)BBATCH * PADL * 3 * HIDD;
    const size_t szSTATE = (size_t)BBATCH * SEQ * HIDD;
    const size_t szPROJ  = (size_t)BBATCH * SEQ * 2 * HIDD;

    const int M_PAD = BBATCH * PADL;   // 4224
    const int M_SEQ = BBATCH * SEQ;    // 4096

    const int padTotal  = BBATCH * PADL * HIDD;
    const int seqTotal  = BBATCH * SEQ * HIDD;

    for (int l = 0; l < 2; l++) {
        for (int d = 0; d < 2; d++) {
            const float* lin_w = d ? bw_lin_w : fw_lin_w;
            const float* lin_b = d ? bw_lin_b : fw_lin_b;
            const float* hw_w  = d ? bw_hw_w  : fw_hw_w;
            const float* hw_b  = d ? bw_hw_b  : fw_hw_b;
            const float* relw  = (d ? bw_rel : fw_rel) + l * (WIDTHW + 1);

            float* xp    = xpB    + (size_t)d * szXP;
            float* qkv   = qkvB   + (size_t)d * szQKV;
            float* attn  = attnB  + (size_t)d * szXP;
            float* fa    = faB    + (size_t)d * szXP;
            float* state = stateB + (size_t)d * szSTATE;
            float* proj  = projB  + (size_t)d * szPROJ;

            const float* src = (l == 0) ? inputs : state;

            // 1. padded input  [B, PAD, HID]
            build_pad_kernel<<<(padTotal + 255) / 256, 256>>>(
                src, fw_pad + l * WIDTHW * HIDD, bw_pad + l * WIDTHW * HIDD, xp);

            // 2. fused QKV GEMM: [4224,512] x [1536,512]^T
            {
                dim3 grid(3 * HIDD / 128, M_PAD / 128);
                gemm_nt_bias<<<grid, 256>>>(xp,
                    lin_w + (size_t)l * 4 * HIDD * HIDD,
                    lin_b + (size_t)l * 4 * HIDD,
                    qkv, M_PAD, 3 * HIDD, HIDD);
            }

            // 3. banded attention
            {
                dim3 grid(PADL / 8, BBATCH * NHEADS);
                band_attn_kernel<<<grid, 256>>>(qkv, attn, d);
            }

            // 4. out-proj GEMM: [4224,512] x [512,512]^T
            {
                dim3 grid(HIDD / 128, M_PAD / 128);
                gemm_nt_bias<<<grid, 256>>>(attn,
                    lin_w + (size_t)(l * 4 + 3) * HIDD * HIDD,
                    lin_b + (size_t)(l * 4 + 3) * HIDD,
                    fa, M_PAD, HIDD, HIDD);
            }

            // 5. rel combine -> state (fo) [B, S, HID]
            rel_combine_kernel<<<(seqTotal + 255) / 256, 256>>>(
                fa, relw, state, d ? WIDTHW : 0);

            // 6. two highway layers
            for (int i = 0; i < 2; i++) {
                dim3 grid(2 * HIDD / 128, M_SEQ / 128);
                gemm_nt_bias<<<grid, 256>>>(state,
                    hw_w + (size_t)(l * 2 + i) * 2 * HIDD * HIDD,
                    hw_b + (size_t)(l * 2 + i) * 2 * HIDD,
                    proj, M_SEQ, 2 * HIDD, HIDD);
                float* outp = (i == 1)
                    ? out + (size_t)l * BBATCH * SEQ * 2 * HIDD
                    : nullptr;
                highway_elem_kernel<<<(seqTotal + 255) / 256, 256>>>(
                    proj, state, outp, d * HIDD);
            }
        }
    }
}

// round 3
// speedup vs baseline: 2.0592x; 2.0592x over previous
#include <cuda_runtime.h>
#include <cuda_fp16.h>
#include <math.h>
#include <stdint.h>

#define WIDTHW 16
#define HIDD 512
#define NHEADS 8
#define DKH 64
#define SEQ 1024
#define BBATCH 4
#define PADL 1056   // SEQ + 2*WIDTH

// ====================== scratch (device globals) ============================
__device__ float g_qkv  [2][(size_t)BBATCH*PADL*3*HIDD];
__device__ float g_fa   [2][(size_t)BBATCH*PADL*HIDD];
__device__ float g_state[2][(size_t)BBATCH*SEQ*HIDD];
__device__ float g_proj [2][(size_t)BBATCH*SEQ*2*HIDD];

// fp16 hi/lo split planes: [dir][2(hi,lo)][elems]
__device__ __half g_xp16  [2][2][(size_t)BBATCH*PADL*HIDD];
__device__ __half g_attn16[2][2][(size_t)BBATCH*PADL*HIDD];
__device__ __half g_st16  [2][2][(size_t)BBATCH*SEQ*HIDD];
__device__ __half g_wlin16[2][2][(size_t)2*4*HIDD*HIDD];
__device__ __half g_whw16 [2][2][(size_t)2*2*2*HIDD*HIDD];

// ====================== helpers =============================================
__device__ __forceinline__ uint32_t smem_u32(const void* p) {
    uint32_t a;
    asm("{ .reg .u64 t; cvta.to.shared.u64 t, %1; cvt.u32.u64 %0, t; }"
        : "=r"(a) : "l"(p));
    return a;
}
__device__ __forceinline__ void split_f16(float x, __half& h, __half& l) {
    h = __float2half_rn(x);
    l = __float2half_rn(x - __half2float(h));
}
__device__ __forceinline__ void mma16816(float* c, const uint32_t* a, const uint32_t* b) {
    asm volatile(
        "mma.sync.aligned.m16n8k16.row.col.f32.f16.f16.f32 "
        "{%0,%1,%2,%3}, {%4,%5,%6,%7}, {%8,%9}, {%0,%1,%2,%3};"
        : "+f"(c[0]), "+f"(c[1]), "+f"(c[2]), "+f"(c[3])
        : "r"(a[0]), "r"(a[1]), "r"(a[2]), "r"(a[3]), "r"(b[0]), "r"(b[1]));
}

// ====================== fp16-split tensor-core GEMM =========================
// C[M,N] = (Ahi+Alo)[M,512] * (Bhi+Blo)[N,512]^T + bias     (lo*lo dropped)
// CTA tile 128x128, BK=32, 2-stage cp.async pipeline.
// smem per stage: 4 matrices x (128 rows x 80 bytes) = 40960 B.
#define SMM 10240
#define SMSTG 40960
#define GSMEM (2 * SMSTG)

__global__ void __launch_bounds__(256, 1)
gemm_mma_kernel(const __half* __restrict__ Ahi, const __half* __restrict__ Alo,
                const __half* __restrict__ Bhi, const __half* __restrict__ Blo,
                const float* __restrict__ bias, float* __restrict__ C, int N)
{
    extern __shared__ char smc[];
    const int tid  = threadIdx.x;
    const int lane = tid & 31, wid = tid >> 5;
    const int wm = wid & 1;        // 2 warps over M
    const int wn = wid >> 1;       // 4 warps over N
    const int m0 = blockIdx.y * 128, n0 = blockIdx.x * 128;
    const int K = HIDD;            // 512

    // ---- cp.async loader mapping: thread -> (row pair, 16B chunk) ----
    const int lr = tid >> 2;       // 0..63
    const int lq = tid & 3;        // 16B chunk within 64B row
    const __half* gsrc[4] = {
        Ahi + (size_t)(m0 + lr) * K + lq * 8,
        Alo + (size_t)(m0 + lr) * K + lq * 8,
        Bhi + (size_t)(n0 + lr) * K + lq * 8,
        Blo + (size_t)(n0 + lr) * K + lq * 8 };
    const uint32_t sb = smem_u32(smc);
    const uint32_t sdst = sb + (uint32_t)lr * 80 + (uint32_t)lq * 16;

#define LOAD_CHUNK(c) do {                                                     \
        uint32_t _st = sdst + ((c) & 1) * SMSTG;                               \
        size_t _ko = (size_t)(c) * 32;                                         \
        _Pragma("unroll")                                                      \
        for (int _m = 0; _m < 4; _m++) {                                       \
            _Pragma("unroll")                                                  \
            for (int _rr = 0; _rr < 2; _rr++) {                                \
                uint32_t _d = _st + _m * SMM + _rr * (64 * 80);                \
                const __half* _s = gsrc[_m] + _ko + (size_t)_rr * 64 * K;      \
                asm volatile("cp.async.cg.shared.global [%0], [%1], 16;"       \
                             :: "r"(_d), "l"(_s));                             \
            }                                                                  \
        }                                                                      \
        asm volatile("cp.async.commit_group;");                               \
    } while (0)

    float acc[4][4][4];
#pragma unroll
    for (int i = 0; i < 4; i++)
#pragma unroll
        for (int j = 0; j < 4; j++)
#pragma unroll
            for (int q = 0; q < 4; q++) acc[i][j][q] = 0.f;

    const int fr = lane >> 2;          // fragment row 0..7
    const int fq = lane & 3;           // fragment quad col

    LOAD_CHUNK(0);

    for (int c = 0; c < 16; c++) {
        if (c + 1 < 16) {
            LOAD_CHUNK(c + 1);
            asm volatile("cp.async.wait_group 1;");
        } else {
            asm volatile("cp.async.wait_group 0;");
        }
        __syncthreads();

        const char* pAh = smc + (c & 1) * SMSTG;
        const char* pAl = pAh + SMM;
        const char* pBh = pAh + 2 * SMM;
        const char* pBl = pAh + 3 * SMM;

#pragma unroll
        for (int ks = 0; ks < 2; ks++) {
            const int kb = ks * 32 + fq * 4;     // byte offset within row
            uint32_t ah[4][4], al[4][4], bh[4][2], bl[4][2];
#pragma unroll
            for (int mf = 0; mf < 4; mf++) {
                const char* p = pAh + (size_t)(wm * 64 + mf * 16 + fr) * 80 + kb;
                ah[mf][0] = *(const uint32_t*)(p);
                ah[mf][1] = *(const uint32_t*)(p + 8 * 80);
                ah[mf][2] = *(const uint32_t*)(p + 16);
                ah[mf][3] = *(const uint32_t*)(p + 8 * 80 + 16);
                const char* q = pAl + (size_t)(wm * 64 + mf * 16 + fr) * 80 + kb;
                al[mf][0] = *(const uint32_t*)(q);
                al[mf][1] = *(const uint32_t*)(q + 8 * 80);
                al[mf][2] = *(const uint32_t*)(q + 16);
                al[mf][3] = *(const uint32_t*)(q + 8 * 80 + 16);
            }
#pragma unroll
            for (int nf = 0; nf < 4; nf++) {
                const char* p = pBh + (size_t)(wn * 32 + nf * 8 + fr) * 80 + kb;
                bh[nf][0] = *(const uint32_t*)(p);
                bh[nf][1] = *(const uint32_t*)(p + 16);
                const char* q = pBl + (size_t)(wn * 32 + nf * 8 + fr) * 80 + kb;
                bl[nf][0] = *(const uint32_t*)(q);
                bl[nf][1] = *(const uint32_t*)(q + 16);
            }
#pragma unroll
            for (int mf = 0; mf < 4; mf++)
#pragma unroll
                for (int nf = 0; nf < 4; nf++) {
                    mma16816(acc[mf][nf], ah[mf], bh[nf]);
                    mma16816(acc[mf][nf], ah[mf], bl[nf]);
                    mma16816(acc[mf][nf], al[mf], bh[nf]);
                }
        }
        __syncthreads();
    }

    // ---- epilogue: add bias, store fp32 ----
#pragma unroll
    for (int mf = 0; mf < 4; mf++) {
        const int row = m0 + wm * 64 + mf * 16 + fr;
#pragma unroll
        for (int nf = 0; nf < 4; nf++) {
            const int col = n0 + wn * 32 + nf * 8 + fq * 2;
            const float b0 = __ldg(&bias[col]);
            const float b1 = __ldg(&bias[col + 1]);
            float2 v0 = {acc[mf][nf][0] + b0, acc[mf][nf][1] + b1};
            float2 v1 = {acc[mf][nf][2] + b0, acc[mf][nf][3] + b1};
            *(float2*)(C + (size_t)row * N + col) = v0;
            *(float2*)(C + (size_t)(row + 8) * N + col) = v1;
        }
    }
#undef LOAD_CHUNK
}

// ====================== small kernels =======================================
__global__ void convert_split_kernel(const float* __restrict__ src,
                                     __half* __restrict__ hi,
                                     __half* __restrict__ lo, int n)
{
    int i = blockIdx.x * 256 + threadIdx.x;
    if (i >= n) return;
    __half h, l;
    split_f16(src[i], h, l);
    hi[i] = h; lo[i] = l;
}

__global__ void build_pad16_kernel(const float* __restrict__ src,
                                   const float* __restrict__ fp,
                                   const float* __restrict__ bp,
                                   __half* __restrict__ hi,
                                   __half* __restrict__ lo)
{
    int idx = blockIdx.x * blockDim.x + threadIdx.x;
    const int total = BBATCH * PADL * HIDD;
    if (idx >= total) return;
    int c = idx % HIDD;
    int t = (idx / HIDD) % PADL;
    int b = idx / (HIDD * PADL);
    float v;
    if (t < WIDTHW)            v = fp[t * HIDD + c];
    else if (t < WIDTHW + SEQ) v = src[((size_t)b * SEQ + (t - WIDTHW)) * HIDD + c];
    else                       v = bp[(t - WIDTHW - SEQ) * HIDD + c];
    __half h, l;
    split_f16(v, h, l);
    hi[idx] = h; lo[idx] = l;
}

__global__ void band_attn_kernel(const float* __restrict__ qkv,
                                 __half* __restrict__ ohi,
                                 __half* __restrict__ olo, int dir)
{
    const int warp = threadIdx.x >> 5;
    const int lane = threadIdx.x & 31;
    const int i = blockIdx.x * 8 + warp;
    if (i >= PADL) return;
    const int bh = blockIdx.y;
    const int b = bh >> 3, h = bh & 7;

    const float* base = qkv + (size_t)b * PADL * (3 * HIDD);
    const int hc = h * DKH + 2 * lane;

    const float q0 = base[(size_t)i * (3 * HIDD) + hc];
    const float q1 = base[(size_t)i * (3 * HIDD) + hc + 1];

    int j0, j1;
    if (dir == 0) { j0 = max(0, i - (WIDTHW + 1)); j1 = i; }
    else          { j0 = i; j1 = min(PADL - 1, i + (WIDTHW + 1)); }

    float s[WIDTHW + 2];
    float mx = -1e30f;
#pragma unroll
    for (int t = 0; t < WIDTHW + 2; t++) {
        int j = j0 + t;
        bool valid = (j <= j1);
        int jc = valid ? j : j1;
        const float* kp = base + (size_t)jc * (3 * HIDD) + HIDD + hc;
        float p = q0 * kp[0] + q1 * kp[1];
#pragma unroll
        for (int o = 16; o > 0; o >>= 1) p += __shfl_xor_sync(0xffffffffu, p, o);
        p *= 0.125f;
        s[t] = valid ? p : -1e30f;
        mx = fmaxf(mx, s[t]);
    }
    float den = 0.f;
#pragma unroll
    for (int t = 0; t < WIDTHW + 2; t++) { s[t] = __expf(s[t] - mx); den += s[t]; }
    const float inv = 1.f / den;

    float o0 = 0.f, o1 = 0.f;
#pragma unroll
    for (int t = 0; t < WIDTHW + 2; t++) {
        int j = j0 + t; if (j > j1) j = j1;
        const float* vp = base + (size_t)j * (3 * HIDD) + 2 * HIDD + hc;
        o0 += s[t] * vp[0];
        o1 += s[t] * vp[1];
    }
    size_t oi = ((size_t)b * PADL + i) * HIDD + hc;
    __half h0, l0, h1, l1;
    split_f16(o0 * inv, h0, l0);
    split_f16(o1 * inv, h1, l1);
    ohi[oi] = h0; olo[oi] = l0;
    ohi[oi + 1] = h1; olo[oi + 1] = l1;
}

__global__ void rel_combine_kernel(const float* __restrict__ fa,
                                   const float* __restrict__ w,
                                   float* __restrict__ fo,
                                   __half* __restrict__ hi,
                                   __half* __restrict__ lo, int off)
{
    int idx = blockIdx.x * blockDim.x + threadIdx.x;
    const int total = BBATCH * SEQ * HIDD;
    if (idx >= total) return;
    int c = idx & (HIDD - 1);
    int t = (idx >> 9) & (SEQ - 1);
    int b = idx >> 19;
    const float* base = fa + (size_t)b * PADL * HIDD + c;
    float acc = base[(size_t)(WIDTHW + t) * HIDD];
#pragma unroll
    for (int k = 0; k <= WIDTHW; k++)
        acc += __ldg(&w[k]) * base[(size_t)(off + t + k) * HIDD];
    fo[idx] = acc;
    __half h, l;
    split_f16(acc, h, l);
    hi[idx] = h; lo[idx] = l;
}

__global__ void highway_elem_kernel(const float* __restrict__ proj,
                                    float* __restrict__ x,
                                    __half* __restrict__ hi,
                                    __half* __restrict__ lo,
                                    float* __restrict__ outp, int coloff)
{
    int idx = blockIdx.x * blockDim.x + threadIdx.x;
    const int total = BBATCH * SEQ * HIDD;
    if (idx >= total) return;
    int r = idx >> 9;
    int c = idx & (HIDD - 1);
    float nl = proj[(size_t)r * (2 * HIDD) + c];
    float gz = proj[(size_t)r * (2 * HIDD) + HIDD + c];
    float g = 1.f / (1.f + __expf(-gz));
    float res = g * x[idx] + (1.f - g) * fmaxf(nl, 0.f);
    x[idx] = res;
    __half h, l;
    split_f16(res, h, l);
    hi[idx] = h; lo[idx] = l;
    if (outp) outp[(size_t)r * (2 * HIDD) + coloff + c] = res;
}

// ====================== host-side GEMM launch ===============================
static void launch_gemm(__half* Ahi, size_t Aplane, int M,
                        __half* Bhi, size_t Bplane, int Ntot,
                        const float* bias, float* C)
{
    dim3 grid(Ntot / 128, M / 128);
    gemm_mma_kernel<<<grid, 256, GSMEM>>>(Ahi, Ahi + Aplane, Bhi, Bhi + Bplane,
                                          bias, C, Ntot);
}

// ====================== launcher ============================================
extern "C" void kernel_launch(void* const* d_in, const int* in_sizes, int n_in,
                              void* d_out, int out_size)
{
    const float* inputs   = (const float*)d_in[0];
    const float* fw_lin_w = (const float*)d_in[2];
    const float* fw_lin_b = (const float*)d_in[3];
    const float* bw_lin_w = (const float*)d_in[4];
    const float* bw_lin_b = (const float*)d_in[5];
    const float* fw_hw_w  = (const float*)d_in[6];
    const float* fw_hw_b  = (const float*)d_in[7];
    const float* bw_hw_w  = (const float*)d_in[8];
    const float* bw_hw_b  = (const float*)d_in[9];
    const float* fw_pad   = (const float*)d_in[10];
    const float* bw_pad   = (const float*)d_in[11];
    const float* fw_rel   = (const float*)d_in[12];
    const float* bw_rel   = (const float*)d_in[13];
    float* out = (float*)d_out;

    cudaFuncSetAttribute(gemm_mma_kernel,
                         cudaFuncAttributeMaxDynamicSharedMemorySize, GSMEM);

    float *qkvB, *faB, *stateB, *projB;
    __half *xp16, *attn16, *st16, *wlin16, *whw16;
    cudaGetSymbolAddress((void**)&qkvB,   g_qkv);
    cudaGetSymbolAddress((void**)&faB,    g_fa);
    cudaGetSymbolAddress((void**)&stateB, g_state);
    cudaGetSymbolAddress((void**)&projB,  g_proj);
    cudaGetSymbolAddress((void**)&xp16,   g_xp16);
    cudaGetSymbolAddress((void**)&attn16, g_attn16);
    cudaGetSymbolAddress((void**)&st16,   g_st16);
    cudaGetSymbolAddress((void**)&wlin16, g_wlin16);
    cudaGetSymbolAddress((void**)&whw16,  g_whw16);

    const size_t szXP  = (size_t)BBATCH * PADL * HIDD;
    const size_t szST  = (size_t)BBATCH * SEQ * HIDD;
    const size_t szLIN = (size_t)2 * 4 * HIDD * HIDD;
    const size_t szHW  = (size_t)2 * 2 * 2 * HIDD * HIDD;

    const int M_PAD = BBATCH * PADL;   // 4224
    const int M_SEQ = BBATCH * SEQ;    // 4096
    const int padTotal = BBATCH * PADL * HIDD;
    const int seqTotal = BBATCH * SEQ * HIDD;

    // weight conversions
    {
        int nblk = (int)((szLIN + 255) / 256);
        convert_split_kernel<<<nblk, 256>>>(fw_lin_w, wlin16,
                                            wlin16 + szLIN, (int)szLIN);
        convert_split_kernel<<<nblk, 256>>>(bw_lin_w, wlin16 + 2 * szLIN,
                                            wlin16 + 3 * szLIN, (int)szLIN);
        convert_split_kernel<<<nblk, 256>>>(fw_hw_w, whw16,
                                            whw16 + szHW, (int)szHW);
        convert_split_kernel<<<nblk, 256>>>(bw_hw_w, whw16 + 2 * szHW,
                                            whw16 + 3 * szHW, (int)szHW);
    }

    for (int l = 0; l < 2; l++) {
        for (int d = 0; d < 2; d++) {
            const float* lin_b = d ? bw_lin_b : fw_lin_b;
            const float* hw_b  = d ? bw_hw_b  : fw_hw_b;
            const float* relw  = (d ? bw_rel : fw_rel) + l * (WIDTHW + 1);

            __half* xpH   = xp16   + (size_t)d * 2 * szXP;
            __half* attnH = attn16 + (size_t)d * 2 * szXP;
            __half* stH   = st16   + (size_t)d * 2 * szST;
            __half* wlH   = wlin16 + (size_t)d * 2 * szLIN;
            __half* whH   = whw16  + (size_t)d * 2 * szHW;

            float* qkv   = qkvB   + (size_t)d * BBATCH * PADL * 3 * HIDD;
            float* fa    = faB    + (size_t)d * szXP;
            float* state = stateB + (size_t)d * szST;
            float* proj  = projB  + (size_t)d * BBATCH * SEQ * 2 * HIDD;

            const float* src = (l == 0) ? inputs : state;

            // 1. padded input -> hi/lo fp16
            build_pad16_kernel<<<(padTotal + 255) / 256, 256>>>(
                src, fw_pad + l * WIDTHW * HIDD, bw_pad + l * WIDTHW * HIDD,
                xpH, xpH + szXP);

            // 2. fused QKV GEMM: [4224,512] x [1536,512]^T
            launch_gemm(xpH, szXP, M_PAD,
                        wlH + (size_t)l * 4 * HIDD * HIDD, szLIN, 3 * HIDD,
                        lin_b + (size_t)l * 4 * HIDD, qkv);

            // 3. banded attention -> hi/lo fp16
            {
                dim3 grid(PADL / 8, BBATCH * NHEADS);
                band_attn_kernel<<<grid, 256>>>(qkv, attnH, attnH + szXP, d);
            }

            // 4. out-proj GEMM: [4224,512] x [512,512]^T
            launch_gemm(attnH, szXP, M_PAD,
                        wlH + (size_t)(l * 4 + 3) * HIDD * HIDD, szLIN, HIDD,
                        lin_b + (size_t)(l * 4 + 3) * HIDD, fa);

            // 5. rel combine -> state fp32 + hi/lo
            rel_combine_kernel<<<(seqTotal + 255) / 256, 256>>>(
                fa, relw, state, stH, stH + szST, d ? WIDTHW : 0);

            // 6. two highway layers
            for (int i = 0; i < 2; i++) {
                launch_gemm(stH, szST, M_SEQ,
                            whH + (size_t)(l * 2 + i) * 2 * HIDD * HIDD, szHW, 2 * HIDD,
                            hw_b + (size_t)(l * 2 + i) * 2 * HIDD, proj);
                float* outp = (i == 1)
                    ? out + (size_t)l * BBATCH * SEQ * 2 * HIDD
                    : nullptr;
                highway_elem_kernel<<<(seqTotal + 255) / 256, 256>>>(
                    proj, state, stH, stH + szST, outp, d * HIDD);
            }
        }
    }
}

// round 4
// speedup vs baseline: 2.6894x; 1.3060x over previous
#include <cuda_runtime.h>
#include <cuda_fp16.h>
#include <math.h>
#include <stdint.h>

#define WIDTHW 16
#define HIDD 512
#define NHEADS 8
#define DKH 64
#define SEQ 1024
#define BBATCH 4
#define PADL 1056   // SEQ + 2*WIDTH

// ====================== scratch (device globals) ============================
__device__ float g_qkv  [2][(size_t)BBATCH*PADL*3*HIDD];
__device__ float g_fa   [2][(size_t)BBATCH*PADL*HIDD];
__device__ float g_state[2][(size_t)BBATCH*SEQ*HIDD];
__device__ float g_proj [2][(size_t)BBATCH*SEQ*2*HIDD];

// fp16 hi/lo split planes: [dir][2(hi,lo)][elems]
__device__ __half g_xp16  [2][2][(size_t)BBATCH*PADL*HIDD];
__device__ __half g_attn16[2][2][(size_t)BBATCH*PADL*HIDD];
__device__ __half g_st16  [2][2][(size_t)BBATCH*SEQ*HIDD];
__device__ __half g_wlin16[2][2][(size_t)2*4*HIDD*HIDD];
__device__ __half g_whw16 [2][2][(size_t)2*2*2*HIDD*HIDD];

// ====================== helpers =============================================
__device__ __forceinline__ uint32_t smem_u32(const void* p) {
    uint32_t a;
    asm("{ .reg .u64 t; cvta.to.shared.u64 t, %1; cvt.u32.u64 %0, t; }"
        : "=r"(a) : "l"(p));
    return a;
}
__device__ __forceinline__ void split_f16(float x, __half& h, __half& l) {
    h = __float2half_rn(x);
    l = __float2half_rn(x - __half2float(h));
}
__device__ __forceinline__ void mma16816(float* c, const uint32_t* a, const uint32_t* b) {
    asm volatile(
        "mma.sync.aligned.m16n8k16.row.col.f32.f16.f16.f32 "
        "{%0,%1,%2,%3}, {%4,%5,%6,%7}, {%8,%9}, {%0,%1,%2,%3};"
        : "+f"(c[0]), "+f"(c[1]), "+f"(c[2]), "+f"(c[3])
        : "r"(a[0]), "r"(a[1]), "r"(a[2]), "r"(a[3]), "r"(b[0]), "r"(b[1]));
}
__device__ __forceinline__ void ldsm4(uint32_t* r, uint32_t addr) {
    asm volatile("ldmatrix.sync.aligned.m8n8.x4.shared.b16 {%0,%1,%2,%3}, [%4];"
        : "=r"(r[0]), "=r"(r[1]), "=r"(r[2]), "=r"(r[3]) : "r"(addr));
}

// ====================== fp16-split tensor-core GEMM =========================
// C[M,N] = (Ahi+Alo)[M,512] * (Bhi+Blo)[N,512]^T + bias     (lo*lo dropped)
// CTA tile 128x128, BK=32, 2-stage cp.async pipeline, ldmatrix fragments.
// smem per stage: 4 matrices x (128 rows x 80 bytes) = 40960 B.
#define SMM 10240
#define SMSTG 40960
#define GSMEM (2 * SMSTG)

__global__ void __launch_bounds__(256, 1)
gemm_mma_kernel(const __half* __restrict__ Ahi, const __half* __restrict__ Alo,
                const __half* __restrict__ Bhi, const __half* __restrict__ Blo,
                const float* __restrict__ bias, float* __restrict__ C, int N)
{
    extern __shared__ char smc[];
    const int tid  = threadIdx.x;
    const int lane = tid & 31, wid = tid >> 5;
    const int wm = wid & 1;        // 2 warps over M
    const int wn = wid >> 1;       // 4 warps over N
    const int m0 = blockIdx.y * 128, n0 = blockIdx.x * 128;
    const int K = HIDD;            // 512

    // ---- cp.async loader mapping ----
    const int lr = tid >> 2;       // 0..63
    const int lq = tid & 3;        // 16B chunk within 64B row
    const __half* gsrc[4] = {
        Ahi + (size_t)(m0 + lr) * K + lq * 8,
        Alo + (size_t)(m0 + lr) * K + lq * 8,
        Bhi + (size_t)(n0 + lr) * K + lq * 8,
        Blo + (size_t)(n0 + lr) * K + lq * 8 };
    const uint32_t sb = smem_u32(smc);
    const uint32_t sdst = sb + (uint32_t)lr * 80 + (uint32_t)lq * 16;

#define LOAD_CHUNK(c) do {                                                     \
        uint32_t _st = sdst + ((c) & 1) * SMSTG;                               \
        size_t _ko = (size_t)(c) * 32;                                         \
        _Pragma("unroll")                                                      \
        for (int _m = 0; _m < 4; _m++) {                                       \
            _Pragma("unroll")                                                  \
            for (int _rr = 0; _rr < 2; _rr++) {                                \
                uint32_t _d = _st + _m * SMM + _rr * (64 * 80);                \
                const __half* _s = gsrc[_m] + _ko + (size_t)_rr * 64 * K;      \
                asm volatile("cp.async.cg.shared.global [%0], [%1], 16;"       \
                             :: "r"(_d), "l"(_s));                             \
            }                                                                  \
        }                                                                      \
        asm volatile("cp.async.commit_group;");                               \
    } while (0)

    float acc[4][4][4];
#pragma unroll
    for (int i = 0; i < 4; i++)
#pragma unroll
        for (int j = 0; j < 4; j++)
#pragma unroll
            for (int q = 0; q < 4; q++) acc[i][j][q] = 0.f;

    const int fr = lane >> 2;          // fragment row 0..7
    const int fq = lane & 3;           // fragment quad col

    // ldmatrix per-lane address offsets (within a matrix plane)
    const int tl = lane >> 3, rw = lane & 7;
    // A x4: t0 (r0-7,k0-7) t1 (r8-15,k0-7) t2 (r0-7,k8-15) t3 (r8-15,k8-15)
    const uint32_t a_off = (uint32_t)((wm * 64 + rw + (tl & 1) * 8) * 80 + (tl >> 1) * 16);
    // B x4 over nf pair: t0 (nf0,k0-7) t1 (nf0,k8-15) t2 (nf1,k0-7) t3 (nf1,k8-15)
    const uint32_t b_off = (uint32_t)((wn * 32 + (tl >> 1) * 8 + rw) * 80 + (tl & 1) * 16);

    LOAD_CHUNK(0);

    for (int c = 0; c < 16; c++) {
        if (c + 1 < 16) {
            LOAD_CHUNK(c + 1);
            asm volatile("cp.async.wait_group 1;");
        } else {
            asm volatile("cp.async.wait_group 0;");
        }
        __syncthreads();

        const uint32_t pAh = sb + (c & 1) * SMSTG;
        const uint32_t pAl = pAh + SMM;
        const uint32_t pBh = pAh + 2 * SMM;
        const uint32_t pBl = pAh + 3 * SMM;

#pragma unroll
        for (int ks = 0; ks < 2; ks++) {
            const uint32_t kb = ks * 32;
            uint32_t ah[4][4], al[4][4], bh[4][2], bl[4][2];
#pragma unroll
            for (int np = 0; np < 2; np++) {
                uint32_t t[4];
                ldsm4(t, pBh + b_off + np * (16 * 80) + kb);
                bh[2 * np][0] = t[0]; bh[2 * np][1] = t[1];
                bh[2 * np + 1][0] = t[2]; bh[2 * np + 1][1] = t[3];
                ldsm4(t, pBl + b_off + np * (16 * 80) + kb);
                bl[2 * np][0] = t[0]; bl[2 * np][1] = t[1];
                bl[2 * np + 1][0] = t[2]; bl[2 * np + 1][1] = t[3];
            }
#pragma unroll
            for (int mf = 0; mf < 4; mf++) {
                ldsm4(ah[mf], pAh + a_off + mf * (16 * 80) + kb);
                ldsm4(al[mf], pAl + a_off + mf * (16 * 80) + kb);
            }
#pragma unroll
            for (int mf = 0; mf < 4; mf++)
#pragma unroll
                for (int nf = 0; nf < 4; nf++) {
                    mma16816(acc[mf][nf], ah[mf], bh[nf]);
                    mma16816(acc[mf][nf], ah[mf], bl[nf]);
                    mma16816(acc[mf][nf], al[mf], bh[nf]);
                }
        }
        __syncthreads();
    }

    // ---- epilogue: add bias, store fp32 ----
#pragma unroll
    for (int mf = 0; mf < 4; mf++) {
        const int row = m0 + wm * 64 + mf * 16 + fr;
#pragma unroll
        for (int nf = 0; nf < 4; nf++) {
            const int col = n0 + wn * 32 + nf * 8 + fq * 2;
            const float b0 = __ldg(&bias[col]);
            const float b1 = __ldg(&bias[col + 1]);
            float2 v0 = {acc[mf][nf][0] + b0, acc[mf][nf][1] + b1};
            float2 v1 = {acc[mf][nf][2] + b0, acc[mf][nf][3] + b1};
            *(float2*)(C + (size_t)row * N + col) = v0;
            *(float2*)(C + (size_t)(row + 8) * N + col) = v1;
        }
    }
#undef LOAD_CHUNK
}

// ====================== small kernels (vectorized x4) =======================
__global__ void convert_split_kernel(const float4* __restrict__ src,
                                     __half2* __restrict__ hi,
                                     __half2* __restrict__ lo, int n4)
{
    int i = blockIdx.x * 256 + threadIdx.x;
    if (i >= n4) return;
    float4 v = src[i];
    __half h0, l0, h1, l1, h2, l2, h3, l3;
    split_f16(v.x, h0, l0); split_f16(v.y, h1, l1);
    split_f16(v.z, h2, l2); split_f16(v.w, h3, l3);
    hi[2 * i]     = __halves2half2(h0, h1);
    hi[2 * i + 1] = __halves2half2(h2, h3);
    lo[2 * i]     = __halves2half2(l0, l1);
    lo[2 * i + 1] = __halves2half2(l2, l3);
}

__global__ void build_pad16_kernel(const float* __restrict__ src,
                                   const float* __restrict__ fp,
                                   const float* __restrict__ bp,
                                   __half2* __restrict__ hi,
                                   __half2* __restrict__ lo)
{
    int idx = blockIdx.x * blockDim.x + threadIdx.x;
    const int total4 = BBATCH * PADL * HIDD / 4;
    if (idx >= total4) return;
    int e = idx * 4;
    int c = e & (HIDD - 1);
    int t = (e >> 9) % PADL;
    int b = e / (HIDD * PADL);
    float4 v;
    if (t < WIDTHW)            v = *(const float4*)(fp + t * HIDD + c);
    else if (t < WIDTHW + SEQ) v = *(const float4*)(src + ((size_t)b * SEQ + (t - WIDTHW)) * HIDD + c);
    else                       v = *(const float4*)(bp + (t - WIDTHW - SEQ) * HIDD + c);
    __half h0, l0, h1, l1, h2, l2, h3, l3;
    split_f16(v.x, h0, l0); split_f16(v.y, h1, l1);
    split_f16(v.z, h2, l2); split_f16(v.w, h3, l3);
    hi[2 * idx]     = __halves2half2(h0, h1);
    hi[2 * idx + 1] = __halves2half2(h2, h3);
    lo[2 * idx]     = __halves2half2(l0, l1);
    lo[2 * idx + 1] = __halves2half2(l2, l3);
}

__global__ void band_attn_kernel(const float* __restrict__ qkv,
                                 __half* __restrict__ ohi,
                                 __half* __restrict__ olo, int dir)
{
    const int warp = threadIdx.x >> 5;
    const int lane = threadIdx.x & 31;
    const int i = blockIdx.x * 8 + warp;
    if (i >= PADL) return;
    const int bh = blockIdx.y;
    const int b = bh >> 3, h = bh & 7;

    const float* base = qkv + (size_t)b * PADL * (3 * HIDD);
    const int hc = h * DKH + 2 * lane;

    const float q0 = base[(size_t)i * (3 * HIDD) + hc];
    const float q1 = base[(size_t)i * (3 * HIDD) + hc + 1];

    int j0, j1;
    if (dir == 0) { j0 = max(0, i - (WIDTHW + 1)); j1 = i; }
    else          { j0 = i; j1 = min(PADL - 1, i + (WIDTHW + 1)); }

    float s[WIDTHW + 2];
    float mx = -1e30f;
#pragma unroll
    for (int t = 0; t < WIDTHW + 2; t++) {
        int j = j0 + t;
        bool valid = (j <= j1);
        int jc = valid ? j : j1;
        const float* kp = base + (size_t)jc * (3 * HIDD) + HIDD + hc;
        float p = q0 * kp[0] + q1 * kp[1];
#pragma unroll
        for (int o = 16; o > 0; o >>= 1) p += __shfl_xor_sync(0xffffffffu, p, o);
        p *= 0.125f;
        s[t] = valid ? p : -1e30f;
        mx = fmaxf(mx, s[t]);
    }
    float den = 0.f;
#pragma unroll
    for (int t = 0; t < WIDTHW + 2; t++) { s[t] = __expf(s[t] - mx); den += s[t]; }
    const float inv = 1.f / den;

    float o0 = 0.f, o1 = 0.f;
#pragma unroll
    for (int t = 0; t < WIDTHW + 2; t++) {
        int j = j0 + t; if (j > j1) j = j1;
        const float* vp = base + (size_t)j * (3 * HIDD) + 2 * HIDD + hc;
        o0 += s[t] * vp[0];
        o1 += s[t] * vp[1];
    }
    size_t oi = ((size_t)b * PADL + i) * HIDD + hc;
    __half h0, l0, h1, l1;
    split_f16(o0 * inv, h0, l0);
    split_f16(o1 * inv, h1, l1);
    ohi[oi] = h0; olo[oi] = l0;
    ohi[oi + 1] = h1; olo[oi + 1] = l1;
}

__global__ void rel_combine_kernel(const float* __restrict__ fa,
                                   const float* __restrict__ w,
                                   float* __restrict__ fo,
                                   __half2* __restrict__ hi,
                                   __half2* __restrict__ lo, int off)
{
    int idx = blockIdx.x * blockDim.x + threadIdx.x;
    const int total4 = BBATCH * SEQ * HIDD / 4;
    if (idx >= total4) return;
    int e = idx * 4;
    int c = e & (HIDD - 1);
    int t = (e >> 9) & (SEQ - 1);
    int b = e >> 19;
    const float* base = fa + (size_t)b * PADL * HIDD + c;
    float4 a = *(const float4*)(base + (size_t)(WIDTHW + t) * HIDD);
#pragma unroll
    for (int k = 0; k <= WIDTHW; k++) {
        float wk = __ldg(&w[k]);
        float4 v = *(const float4*)(base + (size_t)(off + t + k) * HIDD);
        a.x += wk * v.x; a.y += wk * v.y; a.z += wk * v.z; a.w += wk * v.w;
    }
    *(float4*)(fo + e) = a;
    __half h0, l0, h1, l1, h2, l2, h3, l3;
    split_f16(a.x, h0, l0); split_f16(a.y, h1, l1);
    split_f16(a.z, h2, l2); split_f16(a.w, h3, l3);
    hi[2 * idx]     = __halves2half2(h0, h1);
    hi[2 * idx + 1] = __halves2half2(h2, h3);
    lo[2 * idx]     = __halves2half2(l0, l1);
    lo[2 * idx + 1] = __halves2half2(l2, l3);
}

__global__ void highway_elem_kernel(const float* __restrict__ proj,
                                    float* __restrict__ x,
                                    __half2* __restrict__ hi,
                                    __half2* __restrict__ lo,
                                    float* __restrict__ outp, int coloff)
{
    int idx = blockIdx.x * blockDim.x + threadIdx.x;
    const int total4 = BBATCH * SEQ * HIDD / 4;
    if (idx >= total4) return;
    int e = idx * 4;
    int r = e >> 9;
    int c = e & (HIDD - 1);
    float4 nl = *(const float4*)(proj + (size_t)r * (2 * HIDD) + c);
    float4 gz = *(const float4*)(proj + (size_t)r * (2 * HIDD) + HIDD + c);
    float4 xv = *(const float4*)(x + e);
    float4 res;
    {
        float g;
        g = 1.f / (1.f + __expf(-gz.x)); res.x = g * xv.x + (1.f - g) * fmaxf(nl.x, 0.f);
        g = 1.f / (1.f + __expf(-gz.y)); res.y = g * xv.y + (1.f - g) * fmaxf(nl.y, 0.f);
        g = 1.f / (1.f + __expf(-gz.z)); res.z = g * xv.z + (1.f - g) * fmaxf(nl.z, 0.f);
        g = 1.f / (1.f + __expf(-gz.w)); res.w = g * xv.w + (1.f - g) * fmaxf(nl.w, 0.f);
    }
    *(float4*)(x + e) = res;
    __half h0, l0, h1, l1, h2, l2, h3, l3;
    split_f16(res.x, h0, l0); split_f16(res.y, h1, l1);
    split_f16(res.z, h2, l2); split_f16(res.w, h3, l3);
    hi[2 * idx]     = __halves2half2(h0, h1);
    hi[2 * idx + 1] = __halves2half2(h2, h3);
    lo[2 * idx]     = __halves2half2(l0, l1);
    lo[2 * idx + 1] = __halves2half2(l2, l3);
    if (outp) *(float4*)(outp + (size_t)r * (2 * HIDD) + coloff + c) = res;
}

// ====================== host-side GEMM launch ===============================
static void launch_gemm(__half* Ahi, size_t Aplane, int M,
                        __half* Bhi, size_t Bplane, int Ntot,
                        const float* bias, float* C, cudaStream_t st)
{
    dim3 grid(Ntot / 128, M / 128);
    gemm_mma_kernel<<<grid, 256, GSMEM, st>>>(Ahi, Ahi + Aplane, Bhi, Bhi + Bplane,
                                              bias, C, Ntot);
}

// ====================== launcher ============================================
extern "C" void kernel_launch(void* const* d_in, const int* in_sizes, int n_in,
                              void* d_out, int out_size)
{
    const float* inputs   = (const float*)d_in[0];
    const float* fw_lin_w = (const float*)d_in[2];
    const float* fw_lin_b = (const float*)d_in[3];
    const float* bw_lin_w = (const float*)d_in[4];
    const float* bw_lin_b = (const float*)d_in[5];
    const float* fw_hw_w  = (const float*)d_in[6];
    const float* fw_hw_b  = (const float*)d_in[7];
    const float* bw_hw_w  = (const float*)d_in[8];
    const float* bw_hw_b  = (const float*)d_in[9];
    const float* fw_pad   = (const float*)d_in[10];
    const float* bw_pad   = (const float*)d_in[11];
    const float* fw_rel   = (const float*)d_in[12];
    const float* bw_rel   = (const float*)d_in[13];
    float* out = (float*)d_out;

    static bool init_done = false;
    static cudaStream_t s2;
    static cudaEvent_t evF, evJ;
    if (!init_done) {
        cudaFuncSetAttribute(gemm_mma_kernel,
                             cudaFuncAttributeMaxDynamicSharedMemorySize, GSMEM);
        cudaStreamCreateWithFlags(&s2, cudaStreamNonBlocking);
        cudaEventCreateWithFlags(&evF, cudaEventDisableTiming);
        cudaEventCreateWithFlags(&evJ, cudaEventDisableTiming);
        init_done = true;
    }

    float *qkvB, *faB, *stateB, *projB;
    __half *xp16, *attn16, *st16, *wlin16, *whw16;
    cudaGetSymbolAddress((void**)&qkvB,   g_qkv);
    cudaGetSymbolAddress((void**)&faB,    g_fa);
    cudaGetSymbolAddress((void**)&stateB, g_state);
    cudaGetSymbolAddress((void**)&projB,  g_proj);
    cudaGetSymbolAddress((void**)&xp16,   g_xp16);
    cudaGetSymbolAddress((void**)&attn16, g_attn16);
    cudaGetSymbolAddress((void**)&st16,   g_st16);
    cudaGetSymbolAddress((void**)&wlin16, g_wlin16);
    cudaGetSymbolAddress((void**)&whw16,  g_whw16);

    const size_t szXP  = (size_t)BBATCH * PADL * HIDD;
    const size_t szST  = (size_t)BBATCH * SEQ * HIDD;
    const size_t szLIN = (size_t)2 * 4 * HIDD * HIDD;
    const size_t szHW  = (size_t)2 * 2 * 2 * HIDD * HIDD;

    const int M_PAD = BBATCH * PADL;   // 4224
    const int M_SEQ = BBATCH * SEQ;    // 4096
    const int padTotal4 = BBATCH * PADL * HIDD / 4;
    const int seqTotal4 = BBATCH * SEQ * HIDD / 4;

    cudaStream_t s0 = 0;

    // weight conversions: fw on s0 before fork; bw on s2 after fork
    {
        int nblk = (int)((szLIN / 4 + 255) / 256);
        convert_split_kernel<<<nblk, 256, 0, s0>>>((const float4*)fw_lin_w,
            (__half2*)wlin16, (__half2*)(wlin16 + szLIN), (int)(szLIN / 4));
        convert_split_kernel<<<nblk, 256, 0, s0>>>((const float4*)fw_hw_w,
            (__half2*)whw16, (__half2*)(whw16 + szHW), (int)(szHW / 4));
        // fork s2 off the capture stream
        cudaEventRecord(evF, s0);
        cudaStreamWaitEvent(s2, evF, 0);
        convert_split_kernel<<<nblk, 256, 0, s2>>>((const float4*)bw_lin_w,
            (__half2*)(wlin16 + 2 * szLIN), (__half2*)(wlin16 + 3 * szLIN), (int)(szLIN / 4));
        convert_split_kernel<<<nblk, 256, 0, s2>>>((const float4*)bw_hw_w,
            (__half2*)(whw16 + 2 * szHW), (__half2*)(whw16 + 3 * szHW), (int)(szHW / 4));
    }

    for (int l = 0; l < 2; l++) {
        for (int d = 0; d < 2; d++) {
            cudaStream_t st = d ? s2 : s0;
            const float* lin_b = d ? bw_lin_b : fw_lin_b;
            const float* hw_b  = d ? bw_hw_b  : fw_hw_b;
            const float* relw  = (d ? bw_rel : fw_rel) + l * (WIDTHW + 1);

            __half* xpH   = xp16   + (size_t)d * 2 * szXP;
            __half* attnH = attn16 + (size_t)d * 2 * szXP;
            __half* stH   = st16   + (size_t)d * 2 * szST;
            __half* wlH   = wlin16 + (size_t)d * 2 * szLIN;
            __half* whH   = whw16  + (size_t)d * 2 * szHW;

            float* qkv   = qkvB   + (size_t)d * BBATCH * PADL * 3 * HIDD;
            float* fa    = faB    + (size_t)d * szXP;
            float* state = stateB + (size_t)d * szST;
            float* proj  = projB  + (size_t)d * BBATCH * SEQ * 2 * HIDD;

            const float* src = (l == 0) ? inputs : state;

            // 1. padded input -> hi/lo fp16
            build_pad16_kernel<<<(padTotal4 + 255) / 256, 256, 0, st>>>(
                src, fw_pad + l * WIDTHW * HIDD, bw_pad + l * WIDTHW * HIDD,
                (__half2*)xpH, (__half2*)(xpH + szXP));

            // 2. fused QKV GEMM: [4224,512] x [1536,512]^T
            launch_gemm(xpH, szXP, M_PAD,
                        wlH + (size_t)l * 4 * HIDD * HIDD, szLIN, 3 * HIDD,
                        lin_b + (size_t)l * 4 * HIDD, qkv, st);

            // 3. banded attention -> hi/lo fp16
            {
                dim3 grid(PADL / 8, BBATCH * NHEADS);
                band_attn_kernel<<<grid, 256, 0, st>>>(qkv, attnH, attnH + szXP, d);
            }

            // 4. out-proj GEMM: [4224,512] x [512,512]^T
            launch_gemm(attnH, szXP, M_PAD,
                        wlH + (size_t)(l * 4 + 3) * HIDD * HIDD, szLIN, HIDD,
                        lin_b + (size_t)(l * 4 + 3) * HIDD, fa, st);

            // 5. rel combine -> state fp32 + hi/lo
            rel_combine_kernel<<<(seqTotal4 + 255) / 256, 256, 0, st>>>(
                fa, relw, state, (__half2*)stH, (__half2*)(stH + szST), d ? WIDTHW : 0);

            // 6. two highway layers
            for (int i = 0; i < 2; i++) {
                launch_gemm(stH, szST, M_SEQ,
                            whH + (size_t)(l * 2 + i) * 2 * HIDD * HIDD, szHW, 2 * HIDD,
                            hw_b + (size_t)(l * 2 + i) * 2 * HIDD, proj, st);
                float* outp = (i == 1)
                    ? out + (size_t)l * BBATCH * SEQ * 2 * HIDD
                    : nullptr;
                highway_elem_kernel<<<(seqTotal4 + 255) / 256, 256, 0, st>>>(
                    proj, state, (__half2*)stH, (__half2*)(stH + szST), outp, d * HIDD);
            }
        }
    }

    // join: s0 waits for s2 chain
    cudaEventRecord(evJ, s2);
    cudaStreamWaitEvent(s0, evJ, 0);
}